// round 7
// baseline (speedup 1.0000x reference)
#include <cuda_runtime.h>
#include <math.h>

#define NREG 36
#define EMBD 1024
#define SIMD 16
#define HIDD 32
#define NKER 8

__device__ __forceinline__ void dot3(float& q, float& n, float& x, const float4 a, const float4 c) {
    q = fmaf(a.x, a.x, q); q = fmaf(a.y, a.y, q); q = fmaf(a.z, a.z, q); q = fmaf(a.w, a.w, q);
    n = fmaf(c.x, c.x, n); n = fmaf(c.y, c.y, n); n = fmaf(c.z, c.z, n); n = fmaf(c.w, c.w, n);
    x = fmaf(a.x, c.x, x); x = fmaf(a.y, c.y, x); x = fmaf(a.z, c.z, x); x = fmaf(a.w, c.w, x);
}

__global__ void __launch_bounds__(128, 9)
simgsmn_main(const float* __restrict__ inp1, const float* __restrict__ inp2,
             const float* __restrict__ gcn_w, const float* __restrict__ out1_v,
             const float* __restrict__ out1_g, const float* __restrict__ out1_b,
             const float* __restrict__ out2_v, const float* __restrict__ out2_g,
             const float* __restrict__ out2_b, float* __restrict__ out,
             int Bn, int nb2)
{
    __shared__ float sv0[NREG * SIMD];
    __shared__ float sv1[NREG * SIMD];
    __shared__ float W1fs[SIMD * HIDD];
    __shared__ float gs[SIMD * HIDD];     // temp: sum_k gcn_w
    __shared__ float w1t[HIDD * HIDD];    // temp: weight-normed out1
    __shared__ float w2ss[HIDD];
    __shared__ float b1s[HIDD];
    __shared__ float red0[4], red1[4];
    __shared__ float b2sh;

    const int tid  = threadIdx.x;
    const int w    = tid >> 5;
    const int lane = tid & 31;
    const int g    = lane >> 2;     // group owns sim blocks {2g, 2g+1}
    const int c4   = lane & 3;
    const int b    = blockIdx.x;
    const int b2   = b + nb2;
    const int take2 = (b2 < Bn);
    const int b2c  = take2 ? b2 : b;

    // ---- streaming prologue: issue batch-1 loads FIRST (hide constants latency) ----
    const size_t bstride = (size_t)(NREG * EMBD / 4);
    const int loff = w * 256 + g * 32 + c4;
    const float4* p1 = reinterpret_cast<const float4*>(inp1) + (size_t)b * bstride + loff;
    const float4* p2 = reinterpret_cast<const float4*>(inp2) + (size_t)b * bstride + loff;
    const float4* q1 = reinterpret_cast<const float4*>(inp1) + (size_t)b2c * bstride + loff;
    const float4* q2 = reinterpret_cast<const float4*>(inp2) + (size_t)b2c * bstride + loff;

    float4 A0 = __ldcs(p1 +  0), C0 = __ldcs(p2 +  0);
    float4 A1 = __ldcs(p1 +  4), C1 = __ldcs(p2 +  4);
    float4 A2 = __ldcs(p1 +  8), C2 = __ldcs(p2 +  8);
    float4 A3 = __ldcs(p1 + 12), C3 = __ldcs(p2 + 12);

    // ---- per-CTA constant folding (L2-hot after first CTA) ----
    for (int i = tid; i < SIMD * HIDD; i += 128) {
        float a = 0.f;
        #pragma unroll
        for (int k = 0; k < NKER; k++) a += gcn_w[k * SIMD * HIDD + i];
        gs[i] = a;
    }
    if (tid < HIDD) {
        float ss = 0.f;
        #pragma unroll
        for (int h = 0; h < HIDD; h++) { float v = out1_v[tid * HIDD + h]; ss += v * v; }
        const float sc = out1_g[tid] / (sqrtf(ss) + 1e-12f);
        #pragma unroll
        for (int h = 0; h < HIDD; h++) w1t[tid * HIDD + h] = out1_v[tid * HIDD + h] * sc;
        b1s[tid] = out1_b[tid];
    }
    if (tid == 32) {
        float ss = 0.f;
        #pragma unroll
        for (int h = 0; h < HIDD; h++) { float v = out2_v[h]; ss += v * v; }
        const float sc = out2_g[0] / (sqrtf(ss) + 1e-12f);
        #pragma unroll
        for (int h = 0; h < HIDD; h++) w2ss[h] = out2_v[h] * sc * (1.0f / 36.0f);
        b2sh = out2_b[0];
    }
    __syncthreads();
    for (int i = tid; i < SIMD * HIDD; i += 128) {
        const int d = i >> 5, hh = i & 31;
        float acc = 0.f;
        #pragma unroll
        for (int h = 0; h < HIDD; h++)
            acc = fmaf(gs[d * HIDD + h], w1t[hh * HIDD + h], acc);
        W1fs[i] = acc;
    }

    // ---- continuous 18-iteration stream over both batches (no drain at boundary) ----
    #pragma unroll 1
    for (int ii = 0; ii < 18; ii++) {
        const int ib = (ii < 9) ? ii : ii - 9;
        const int i  = w + ib * 4;
        float* svb = (ii < 9) ? sv0 : sv1;
        const float4 *np1, *np2;
        if (ii == 8)       { np1 = q1;        np2 = q2; }
        else if (ii == 17) { np1 = p1;        np2 = p2; }      // clamp (discarded)
        else               { np1 = p1 + 1024; np2 = p2 + 1024; }

        float aq0 = 0.f, an0 = 0.f, ax0 = 0.f, aq1 = 0.f, an1 = 0.f, ax1 = 0.f;
        { float4 a = A0, c = C0; A0 = __ldcs(p1 + 16); C0 = __ldcs(p2 + 16); dot3(aq0, an0, ax0, a, c); }
        { float4 a = A1, c = C1; A1 = __ldcs(p1 + 20); C1 = __ldcs(p2 + 20); dot3(aq0, an0, ax0, a, c); }
        { float4 a = A2, c = C2; A2 = __ldcs(p1 + 24); C2 = __ldcs(p2 + 24); dot3(aq0, an0, ax0, a, c); }
        { float4 a = A3, c = C3; A3 = __ldcs(p1 + 28); C3 = __ldcs(p2 + 28); dot3(aq0, an0, ax0, a, c); }
        { float4 a = A0, c = C0; A0 = __ldcs(np1 +  0); C0 = __ldcs(np2 +  0); dot3(aq1, an1, ax1, a, c); }
        { float4 a = A1, c = C1; A1 = __ldcs(np1 +  4); C1 = __ldcs(np2 +  4); dot3(aq1, an1, ax1, a, c); }
        { float4 a = A2, c = C2; A2 = __ldcs(np1 +  8); C2 = __ldcs(np2 +  8); dot3(aq1, an1, ax1, a, c); }
        { float4 a = A3, c = C3; A3 = __ldcs(np1 + 12); C3 = __ldcs(np2 + 12); dot3(aq1, an1, ax1, a, c); }

        #pragma unroll
        for (int m = 1; m < 4; m <<= 1) {
            aq0 += __shfl_xor_sync(0xffffffffu, aq0, m);
            an0 += __shfl_xor_sync(0xffffffffu, an0, m);
            ax0 += __shfl_xor_sync(0xffffffffu, ax0, m);
            aq1 += __shfl_xor_sync(0xffffffffu, aq1, m);
            an1 += __shfl_xor_sync(0xffffffffu, an1, m);
            ax1 += __shfl_xor_sync(0xffffffffu, ax1, m);
        }
        if (c4 == 0) {
            svb[i * SIMD + 2 * g]     = ax0 / ((sqrtf(aq0) + 1e-8f) * (sqrtf(an0) + 1e-8f));
            svb[i * SIMD + 2 * g + 1] = ax1 / ((sqrtf(aq1) + 1e-8f) * (sqrtf(an1) + 1e-8f));
        }
        p1 = np1; p2 = np2;
    }
    __syncthreads();

    // ---- fused tails for both batches ----
    float part0 = 0.f, part1 = 0.f;
    #pragma unroll
    for (int qq = 0; qq < 9; qq++) {
        const int p = tid + qq * 128;
        const int i = p >> 5, hh = p & 31;
        float acc0 = b1s[hh], acc1 = b1s[hh];
        #pragma unroll
        for (int d = 0; d < SIMD; d++) {
            const float wv = W1fs[d * HIDD + hh];
            acc0 = fmaf(sv0[i * SIMD + d], wv, acc0);
            acc1 = fmaf(sv1[i * SIMD + d], wv, acc1);
        }
        part0 = fmaf(w2ss[hh], tanhf(acc0), part0);
        part1 = fmaf(w2ss[hh], tanhf(acc1), part1);
    }
    #pragma unroll
    for (int m = 1; m < 32; m <<= 1) {
        part0 += __shfl_xor_sync(0xffffffffu, part0, m);
        part1 += __shfl_xor_sync(0xffffffffu, part1, m);
    }
    if (lane == 0) { red0[w] = part0; red1[w] = part1; }
    __syncthreads();
    if (tid == 0) {
        out[b] = b2sh + red0[0] + red0[1] + red0[2] + red0[3];
        if (take2) out[b2] = b2sh + red1[0] + red1[1] + red1[2] + red1[3];
    }
}

extern "C" void kernel_launch(void* const* d_in, const int* in_sizes, int n_in,
                              void* d_out, int out_size) {
    const int Bn  = in_sizes[0] / (NREG * EMBD);
    const int nb2 = (Bn + 1) / 2;
    simgsmn_main<<<nb2, 128>>>(
        (const float*)d_in[0], (const float*)d_in[1], (const float*)d_in[4],
        (const float*)d_in[5], (const float*)d_in[6], (const float*)d_in[7],
        (const float*)d_in[8], (const float*)d_in[9], (const float*)d_in[10],
        (float*)d_out, Bn, nb2);
}